// round 1
// baseline (speedup 1.0000x reference)
#include <cuda_runtime.h>
#include <cuda_bf16.h>
#include <cfloat>
#include <cmath>

// Problem constants
#define BB 32
#define NN 256
#define LL 50
#define BN (BB * NN)          // 8192
#define DU 32
#define DI 32
#define DC 16
#define DD 48                 // item feat size
#define FEAT 128              // DU + 2*DI + 2*DC

// Scratch (no allocation allowed)
__device__ float g_feat[BN * FEAT];
__device__ float g_logits[BN];

// ---------------------------------------------------------------------------
// K1: per-(b,n) attention + pooling. Folded math:
//   M[k][j]  = W1b[k][j] - W1c[k][j] + q[k]*W1d[k][j]
//   cn[j]    = b1[j] + sum_k q[k]*(W1a[k][j] + W1c[k][j])
//   h1[j]    = relu( sum_k he[k]*M[k][j] + cn[j] )
//   v[j]     = sum_m w2[j][m]*w3[m] ;  cs = b2.w3 + b3
//   score    = sum_j h1[j]*v[j] + cs   (zeroed where interest_items==0)
//   pooled  += score * he
// ---------------------------------------------------------------------------
__global__ void __launch_bounds__(256, 2) attn_kernel(
    const float* __restrict__ emb_user,
    const float* __restrict__ emb_item,
    const float* __restrict__ emb_cate,
    const float* __restrict__ w1, const float* __restrict__ b1,
    const float* __restrict__ w2, const float* __restrict__ b2,
    const float* __restrict__ w3, const float* __restrict__ b3,
    const int* __restrict__ user,
    const int* __restrict__ items,
    const int* __restrict__ items_cate,
    const int* __restrict__ ii,     // interest_items   [BN*LL]
    const int* __restrict__ iic)    // interest_cate    [BN*LL]
{
    const int bn   = blockIdx.x;
    const int t    = threadIdx.x;
    const int g    = t >> 6;        // group 0..3 (one l per group)
    const int j    = t & 63;        // output column within group
    const int wid  = t >> 5;
    const int lane = t & 31;

    __shared__ __align__(16) float q_s[DD];
    __shared__ __align__(16) float he_s[4][DD];
    __shared__ __align__(16) float pooled_s[4][DD];
    __shared__ float sred[8];

    // gather q = ie = [emb_item[items], emb_cate[items_cate]]
    const int it = items[bn];
    const int ic = items_cate[bn];
    if (t < 32)       q_s[t] = emb_item[it * DI + t];
    else if (t < 48)  q_s[t] = emb_cate[ic * DC + (t - 32)];
    if (t < 4 * DD)   ((float*)pooled_s)[t] = 0.0f;
    __syncthreads();

    // Per-thread column of folded weight matrix + biases (registers)
    float M[DD];
    float cn = b1[j];
#pragma unroll
    for (int k = 0; k < DD; k++) {
        float qk = q_s[k];
        float a  = w1[(k)        * 64 + j];
        float bb = w1[(48 + k)   * 64 + j];
        float c  = w1[(96 + k)   * 64 + j];
        float d  = w1[(144 + k)  * 64 + j];
        M[k] = bb - c + qk * d;
        cn  += qk * (a + c);
    }
    float v = 0.0f;
#pragma unroll
    for (int m = 0; m < 16; m++) v += w2[j * 16 + m] * w3[m];
    float cs = b3[0];
#pragma unroll
    for (int m = 0; m < 16; m++) cs += b2[m] * w3[m];

    // l loop: 4 l's per iteration (one per 64-thread group)
    for (int lb = 0; lb < LL; lb += 4) {
        const int l = lb + g;
        const bool valid = (l < LL);
        int iidx = 0;

        __syncthreads();   // he_s / sred safe to overwrite
        if (valid) {
            iidx = ii[bn * LL + l];
            int icdx = iic[bn * LL + l];
            if (j < 32)      he_s[g][j] = emb_item[iidx * DI + j];
            else if (j < 48) he_s[g][j] = emb_cate[icdx * DC + (j - 32)];
        }
        __syncthreads();

        // h1_j then score contribution
        float acc = cn;
        const float4* hp = (const float4*)he_s[g];
#pragma unroll
        for (int kk = 0; kk < 12; kk++) {
            float4 h4 = hp[kk];
            acc = fmaf(h4.x, M[kk * 4 + 0], acc);
            acc = fmaf(h4.y, M[kk * 4 + 1], acc);
            acc = fmaf(h4.z, M[kk * 4 + 2], acc);
            acc = fmaf(h4.w, M[kk * 4 + 3], acc);
        }
        float rs = fmaxf(acc, 0.0f) * v;
#pragma unroll
        for (int o = 16; o > 0; o >>= 1)
            rs += __shfl_down_sync(0xffffffffu, rs, o);
        if (lane == 0) sred[wid] = rs;
        __syncthreads();

        float score = sred[2 * g] + sred[2 * g + 1] + cs;
        if (valid && iidx != 0 && j < DD)
            pooled_s[g][j] += score * he_s[g][j];
    }
    __syncthreads();

    // feat = [ie(48), pooled(48), u(32)]
    float* fo = g_feat + bn * FEAT;
    if (t < 48) {
        fo[t] = q_s[t];
    } else if (t < 96) {
        int d = t - 48;
        fo[t] = pooled_s[0][d] + pooled_s[1][d] + pooled_s[2][d] + pooled_s[3][d];
    } else if (t < 128) {
        int uidx = user[bn];
        fo[t] = emb_user[uidx * DU + (t - 96)];
    }
}

// ---------------------------------------------------------------------------
// K2: batched FC MLP: 128 -> 200 relu -> 80 relu -> 1 sigmoid
// 16 rows per CTA, rows staged in smem so weights amortize.
// ---------------------------------------------------------------------------
#define ROWS 16
__global__ void __launch_bounds__(256) fc_kernel(
    const float* __restrict__ fw1, const float* __restrict__ fb1,
    const float* __restrict__ fw2, const float* __restrict__ fb2,
    const float* __restrict__ fw3, const float* __restrict__ fb3)
{
    const int t = threadIdx.x;
    const int row0 = blockIdx.x * ROWS;

    __shared__ __align__(16) float fs[ROWS][FEAT];   // 8 KB
    __shared__ float x1[ROWS][200];                  // 12.8 KB
    __shared__ float x2[ROWS][80];                   // 5.1 KB

    // load feat tile (contiguous)
    const float4* src = (const float4*)(g_feat + row0 * FEAT);
    float4* dst = (float4*)&fs[0][0];
    for (int i = t; i < ROWS * FEAT / 4; i += 256) dst[i] = src[i];
    __syncthreads();

    // fc1: 16 x 200 outputs
    for (int idx = t; idx < ROWS * 200; idx += 256) {
        int r = idx / 200, jj = idx % 200;
        float acc = fb1[jj];
#pragma unroll 8
        for (int i = 0; i < FEAT; i++)
            acc = fmaf(fs[r][i], fw1[i * 200 + jj], acc);
        x1[r][jj] = fmaxf(acc, 0.0f);
    }
    __syncthreads();

    // fc2: 16 x 80 outputs
    for (int idx = t; idx < ROWS * 80; idx += 256) {
        int r = idx / 80, jj = idx % 80;
        float acc = fb2[jj];
#pragma unroll 8
        for (int i = 0; i < 200; i++)
            acc = fmaf(x1[r][i], fw2[i * 80 + jj], acc);
        x2[r][jj] = fmaxf(acc, 0.0f);
    }
    __syncthreads();

    // fc3 + sigmoid
    if (t < ROWS) {
        float acc = fb3[0];
#pragma unroll 8
        for (int i = 0; i < 80; i++)
            acc = fmaf(x2[t][i], fw3[i], acc);
        g_logits[row0 + t] = 1.0f / (1.0f + expf(-acc));
    }
}

// ---------------------------------------------------------------------------
// K3: masked softmax over N=256 per batch row
// ---------------------------------------------------------------------------
__global__ void __launch_bounds__(256) softmax_kernel(
    const int* __restrict__ items, float* __restrict__ out)
{
    const int b = blockIdx.x;
    const int t = threadIdx.x;
    const int wid = t >> 5, lane = t & 31;

    __shared__ float red[8];
    __shared__ float s_mx, s_sum;

    float l = g_logits[b * NN + t];
    bool masked = (items[b * NN + t] == 0);
    float val = masked ? -FLT_MAX : l;

    // block max
    float mx = val;
#pragma unroll
    for (int o = 16; o > 0; o >>= 1)
        mx = fmaxf(mx, __shfl_down_sync(0xffffffffu, mx, o));
    if (lane == 0) red[wid] = mx;
    __syncthreads();
    if (t == 0) {
        float m = red[0];
#pragma unroll
        for (int w = 1; w < 8; w++) m = fmaxf(m, red[w]);
        s_mx = m;
    }
    __syncthreads();
    float m = s_mx;

    float e = masked ? 0.0f : expf(l - m);
    float sum = e;
#pragma unroll
    for (int o = 16; o > 0; o >>= 1)
        sum += __shfl_down_sync(0xffffffffu, sum, o);
    if (lane == 0) red[wid] = sum;
    __syncthreads();
    if (t == 0) {
        float s = 0.0f;
#pragma unroll
        for (int w = 0; w < 8; w++) s += red[w];
        s_sum = s;
    }
    __syncthreads();

    out[b * NN + t] = e / s_sum;
}

// ---------------------------------------------------------------------------
// launch
// Input order (metadata): emb_user, emb_item, emb_cate,
//   att_w1, att_b1, att_w2, att_b2, att_w3, att_b3,
//   fc_w1, fc_b1, fc_w2, fc_b2, fc_w3, fc_b3,
//   user, items, items_cate, interest_items, interest_items_cate
// ---------------------------------------------------------------------------
extern "C" void kernel_launch(void* const* d_in, const int* in_sizes, int n_in,
                              void* d_out, int out_size)
{
    const float* emb_user  = (const float*)d_in[0];
    const float* emb_item  = (const float*)d_in[1];
    const float* emb_cate  = (const float*)d_in[2];
    const float* att_w1    = (const float*)d_in[3];
    const float* att_b1    = (const float*)d_in[4];
    const float* att_w2    = (const float*)d_in[5];
    const float* att_b2    = (const float*)d_in[6];
    const float* att_w3    = (const float*)d_in[7];
    const float* att_b3    = (const float*)d_in[8];
    const float* fc_w1     = (const float*)d_in[9];
    const float* fc_b1     = (const float*)d_in[10];
    const float* fc_w2     = (const float*)d_in[11];
    const float* fc_b2     = (const float*)d_in[12];
    const float* fc_w3     = (const float*)d_in[13];
    const float* fc_b3     = (const float*)d_in[14];
    const int*   user      = (const int*)d_in[15];
    const int*   items     = (const int*)d_in[16];
    const int*   items_cate= (const int*)d_in[17];
    const int*   ii        = (const int*)d_in[18];
    const int*   iic       = (const int*)d_in[19];
    float* out = (float*)d_out;

    attn_kernel<<<BN, 256>>>(emb_user, emb_item, emb_cate,
                             att_w1, att_b1, att_w2, att_b2, att_w3, att_b3,
                             user, items, items_cate, ii, iic);
    fc_kernel<<<BN / ROWS, 256>>>(fc_w1, fc_b1, fc_w2, fc_b2, fc_w3, fc_b3);
    softmax_kernel<<<BB, 256>>>(items, out);
}

// round 2
// speedup vs baseline: 1.6487x; 1.6487x over previous
#include <cuda_runtime.h>
#include <cuda_bf16.h>
#include <cfloat>
#include <cmath>

#define BB 32
#define NN 256
#define LL 50
#define BN (BB * NN)          // 8192
#define DU 32
#define DI 32
#define DC 16
#define DD 48
#define FEAT 128

// ---------------- scratch (no allocs allowed) ----------------
__device__ float g_feat[BN * FEAT];
__device__ float g_logits[BN];
// folded attention weights (setup kernel fills these each launch)
__device__ __align__(16) float g_WbcT[64 * 48];  // [j][k] = w1b - w1c
__device__ __align__(16) float g_WacT[64 * 48];  // [j][k] = w1a + w1c
__device__ __align__(16) float g_WdT [64 * 48];  // [j][k] = w1d
__device__ float g_v[64];                        // w2 @ w3
__device__ float g_cs[1];                        // b2.w3 + b3

// ---------------- f32x2 helpers (sm_100+) ----------------
__device__ __forceinline__ void ffma2(unsigned long long& acc,
                                      unsigned long long a,
                                      unsigned long long b) {
    asm("fma.rn.f32x2 %0, %1, %2, %0;" : "+l"(acc) : "l"(a), "l"(b));
}
__device__ __forceinline__ void upk(unsigned long long v, float& x, float& y) {
    asm("mov.b64 {%0,%1}, %2;" : "=f"(x), "=f"(y) : "l"(v));
}
__device__ __forceinline__ unsigned sptr(const void* p) {
    return (unsigned)__cvta_generic_to_shared(p);
}
__device__ __forceinline__ void lds_v2u64(unsigned addr,
                                          unsigned long long& a,
                                          unsigned long long& b) {
    asm("ld.shared.v2.u64 {%0,%1}, [%2];" : "=l"(a), "=l"(b) : "r"(addr));
}

// ---------------- K0: fold weights ----------------
__global__ void setup_kernel(const float* __restrict__ w1,
                             const float* __restrict__ w2,
                             const float* __restrict__ w3,
                             const float* __restrict__ b2,
                             const float* __restrict__ b3)
{
    int e = blockIdx.x * 256 + threadIdx.x;
    if (blockIdx.x < 12) {  // 3072 elements
        int j = e / 48, k = e % 48;
        float a = w1[k * 64 + j];
        float b = w1[(48 + k) * 64 + j];
        float c = w1[(96 + k) * 64 + j];
        float d = w1[(144 + k) * 64 + j];
        g_WbcT[j * 48 + k] = b - c;
        g_WacT[j * 48 + k] = a + c;
        g_WdT [j * 48 + k] = d;
    } else {
        int t = threadIdx.x;
        if (t < 64) {
            float v = 0.f;
#pragma unroll
            for (int m = 0; m < 16; m++) v += w2[t * 16 + m] * w3[m];
            g_v[t] = v;
        } else if (t == 64) {
            float cs = b3[0];
#pragma unroll
            for (int m = 0; m < 16; m++) cs += b2[m] * w3[m];
            g_cs[0] = cs;
        }
    }
}

// ---------------- K1: attention, one CTA (64 thr) per (b,n) ----------------
__global__ void __launch_bounds__(64) attn_kernel(
    const float* __restrict__ emb_user,
    const float* __restrict__ emb_item,
    const float* __restrict__ emb_cate,
    const float* __restrict__ b1,
    const int* __restrict__ user,
    const int* __restrict__ items,
    const int* __restrict__ items_cate,
    const int* __restrict__ ii,
    const int* __restrict__ iic)
{
    const int bn = blockIdx.x;
    const int u  = threadIdx.x;   // 0..63

    __shared__ __align__(16) float M_s[64][52];    // folded matrix, row j
    __shared__ __align__(16) float he_s[LL][52];   // he rows; col 48 = score
    __shared__ __align__(16) float q_s[48];
    __shared__ float cn_s[64];
    __shared__ float v_s[64];
    __shared__ int   idx_s[LL];

    // ---- load q, v ----
    const int it = items[bn];
    const int ic = items_cate[bn];
    if (u < 32)       q_s[u] = emb_item[it * DI + u];
    else if (u < 48)  q_s[u] = emb_cate[ic * DC + (u - 32)];
    v_s[u] = g_v[u];
    __syncthreads();

    // ---- fold M[j][k] = Wbc + q[k]*Wd ; cn[j] = b1[j] + q.Wac ----
    {
        const int j = u;
        float cn = b1[j];
        const float4* wbc = (const float4*)(g_WbcT + j * 48);
        const float4* wac = (const float4*)(g_WacT + j * 48);
        const float4* wd  = (const float4*)(g_WdT  + j * 48);
        const float4* q4  = (const float4*)q_s;
#pragma unroll
        for (int c = 0; c < 12; c++) {
            float4 qb = q4[c];
            float4 fb = wbc[c], fa = wac[c], fd = wd[c];
            float4 m;
            m.x = fmaf(qb.x, fd.x, fb.x);
            m.y = fmaf(qb.y, fd.y, fb.y);
            m.z = fmaf(qb.z, fd.z, fb.z);
            m.w = fmaf(qb.w, fd.w, fb.w);
            *(float4*)&M_s[j][c * 4] = m;
            cn = fmaf(qb.x, fa.x, cn);
            cn = fmaf(qb.y, fa.y, cn);
            cn = fmaf(qb.z, fa.z, cn);
            cn = fmaf(qb.w, fa.w, cn);
        }
        cn_s[j] = cn;
    }

    // ---- cooperative gather of he into smem (600 float4 chunks) ----
    for (int idx = u; idx < LL * 12; idx += 64) {
        int row = idx / 12, c = idx % 12;
        int iidx = ii[bn * LL + row];
        if (c == 0) idx_s[row] = iidx;
        float4 val;
        if (c < 8) {
            val = *(const float4*)(emb_item + (size_t)iidx * DI + c * 4);
            *(float4*)&he_s[row][c * 4] = val;
        } else {
            int icd = iic[bn * LL + row];
            val = *(const float4*)(emb_cate + (size_t)icd * DC + (c - 8) * 4);
            *(float4*)&he_s[row][32 + (c - 8) * 4] = val;
        }
    }
    __syncthreads();

    // ---- per-thread l: full score ----
    if (u < LL) {
        const int l = u;
        // copy he row into packed f32x2 registers
        unsigned long long he2[24];
        unsigned hb = sptr(&he_s[l][0]);
#pragma unroll
        for (int c = 0; c < 12; c++)
            lds_v2u64(hb + c * 16, he2[2 * c], he2[2 * c + 1]);

        float score = g_cs[0];
        const unsigned mb = sptr(&M_s[0][0]);
#pragma unroll 2
        for (int j = 0; j < 64; j += 2) {
            unsigned ra = mb + j * 208;        // 52 floats * 4B
            unsigned rb = ra + 208;
            unsigned long long acc0 = 0ull, acc1 = 0ull;
#pragma unroll
            for (int c = 0; c < 12; c++) {
                unsigned long long m00, m01, m10, m11;
                lds_v2u64(ra + c * 16, m00, m01);
                lds_v2u64(rb + c * 16, m10, m11);
                ffma2(acc0, he2[2 * c],     m00);
                ffma2(acc0, he2[2 * c + 1], m01);
                ffma2(acc1, he2[2 * c],     m10);
                ffma2(acc1, he2[2 * c + 1], m11);
            }
            float x0, y0, x1, y1;
            upk(acc0, x0, y0);
            upk(acc1, x1, y1);
            float h0 = fmaxf(x0 + y0 + cn_s[j], 0.f);
            float h1 = fmaxf(x1 + y1 + cn_s[j + 1], 0.f);
            score = fmaf(h0, v_s[j], score);
            score = fmaf(h1, v_s[j + 1], score);
        }
        if (idx_s[l] == 0) score = 0.f;
        he_s[l][48] = score;
    }
    __syncthreads();

    // ---- pooled + feat ----
    float* fo = g_feat + bn * FEAT;
    if (u < 48) {
        float pooled = 0.f;
#pragma unroll 10
        for (int l = 0; l < LL; l++)
            pooled = fmaf(he_s[l][48], he_s[l][u], pooled);
        fo[u]      = q_s[u];
        fo[48 + u] = pooled;
    }
    if (u < 32) {
        int uidx = user[bn];
        fo[96 + u] = emb_user[(size_t)uidx * DU + u];
    }
}

// ---------------- K2: FC MLP 128->200->80->1 ----------------
#define ROWS 16
__global__ void __launch_bounds__(256) fc_kernel(
    const float* __restrict__ fw1, const float* __restrict__ fb1,
    const float* __restrict__ fw2, const float* __restrict__ fb2,
    const float* __restrict__ fw3, const float* __restrict__ fb3)
{
    const int t = threadIdx.x;
    const int row0 = blockIdx.x * ROWS;

    __shared__ __align__(16) float fs[ROWS][FEAT];
    __shared__ float x1[ROWS][200];
    __shared__ float x2[ROWS][80];

    const float4* src = (const float4*)(g_feat + row0 * FEAT);
    float4* dst = (float4*)&fs[0][0];
    for (int i = t; i < ROWS * FEAT / 4; i += 256) dst[i] = src[i];
    __syncthreads();

    for (int idx = t; idx < ROWS * 200; idx += 256) {
        int r = idx / 200, jj = idx % 200;
        float acc = fb1[jj];
#pragma unroll 8
        for (int i = 0; i < FEAT; i++)
            acc = fmaf(fs[r][i], fw1[i * 200 + jj], acc);
        x1[r][jj] = fmaxf(acc, 0.0f);
    }
    __syncthreads();

    for (int idx = t; idx < ROWS * 80; idx += 256) {
        int r = idx / 80, jj = idx % 80;
        float acc = fb2[jj];
#pragma unroll 8
        for (int i = 0; i < 200; i++)
            acc = fmaf(x1[r][i], fw2[i * 80 + jj], acc);
        x2[r][jj] = fmaxf(acc, 0.0f);
    }
    __syncthreads();

    if (t < ROWS) {
        float acc = fb3[0];
#pragma unroll 8
        for (int i = 0; i < 80; i++)
            acc = fmaf(x2[t][i], fw3[i], acc);
        g_logits[row0 + t] = 1.0f / (1.0f + expf(-acc));
    }
}

// ---------------- K3: masked softmax over N=256 ----------------
__global__ void __launch_bounds__(256) softmax_kernel(
    const int* __restrict__ items, float* __restrict__ out)
{
    const int b = blockIdx.x;
    const int t = threadIdx.x;
    const int wid = t >> 5, lane = t & 31;

    __shared__ float red[8];
    __shared__ float s_mx, s_sum;

    float l = g_logits[b * NN + t];
    bool masked = (items[b * NN + t] == 0);
    float val = masked ? -FLT_MAX : l;

    float mx = val;
#pragma unroll
    for (int o = 16; o > 0; o >>= 1)
        mx = fmaxf(mx, __shfl_down_sync(0xffffffffu, mx, o));
    if (lane == 0) red[wid] = mx;
    __syncthreads();
    if (t == 0) {
        float m = red[0];
#pragma unroll
        for (int w = 1; w < 8; w++) m = fmaxf(m, red[w]);
        s_mx = m;
    }
    __syncthreads();
    float m = s_mx;

    float e = masked ? 0.0f : expf(l - m);
    float sum = e;
#pragma unroll
    for (int o = 16; o > 0; o >>= 1)
        sum += __shfl_down_sync(0xffffffffu, sum, o);
    if (lane == 0) red[wid] = sum;
    __syncthreads();
    if (t == 0) {
        float s = 0.0f;
#pragma unroll
        for (int w = 0; w < 8; w++) s += red[w];
        s_sum = s;
    }
    __syncthreads();

    out[b * NN + t] = e / s_sum;
}

// ---------------- launch ----------------
extern "C" void kernel_launch(void* const* d_in, const int* in_sizes, int n_in,
                              void* d_out, int out_size)
{
    const float* emb_user  = (const float*)d_in[0];
    const float* emb_item  = (const float*)d_in[1];
    const float* emb_cate  = (const float*)d_in[2];
    const float* att_w1    = (const float*)d_in[3];
    const float* att_b1    = (const float*)d_in[4];
    const float* att_w2    = (const float*)d_in[5];
    const float* att_b2    = (const float*)d_in[6];
    const float* att_w3    = (const float*)d_in[7];
    const float* att_b3    = (const float*)d_in[8];
    const float* fc_w1     = (const float*)d_in[9];
    const float* fc_b1     = (const float*)d_in[10];
    const float* fc_w2     = (const float*)d_in[11];
    const float* fc_b2     = (const float*)d_in[12];
    const float* fc_w3     = (const float*)d_in[13];
    const float* fc_b3     = (const float*)d_in[14];
    const int*   user      = (const int*)d_in[15];
    const int*   items     = (const int*)d_in[16];
    const int*   items_cate= (const int*)d_in[17];
    const int*   ii        = (const int*)d_in[18];
    const int*   iic       = (const int*)d_in[19];
    float* out = (float*)d_out;

    setup_kernel<<<13, 256>>>(att_w1, att_w2, att_w3, att_b2, att_b3);
    attn_kernel<<<BN, 64>>>(emb_user, emb_item, emb_cate, att_b1,
                            user, items, items_cate, ii, iic);
    fc_kernel<<<BN / ROWS, 256>>>(fc_w1, fc_b1, fc_w2, fc_b2, fc_w3, fc_b3);
    softmax_kernel<<<BB, 256>>>(items, out);
}

// round 3
// speedup vs baseline: 1.9681x; 1.1937x over previous
#include <cuda_runtime.h>
#include <cuda_bf16.h>
#include <cfloat>
#include <cmath>

#define BB 32
#define NN 256
#define LL 50
#define BN (BB * NN)          // 8192
#define DU 32
#define DI 32
#define DC 16
#define DD 48
#define FEAT 128

// ---------------- scratch (no allocs allowed) ----------------
__device__ float g_feat[BN * FEAT];
__device__ float g_logits[BN];
// folded attention weights (setup kernel fills these each launch)
__device__ __align__(16) float g_WbcT[64 * 48];  // [j][k] = w1b - w1c
__device__ __align__(16) float g_WacT[64 * 48];  // [j][k] = w1a + w1c
__device__ __align__(16) float g_WdT [64 * 48];  // [j][k] = w1d
__device__ float g_v[64];                        // w2 @ w3
__device__ float g_cs[1];                        // b2.w3 + b3

// ---------------- f32x2 helpers (sm_100+) ----------------
__device__ __forceinline__ void ffma2(unsigned long long& acc,
                                      unsigned long long a,
                                      unsigned long long b) {
    asm("fma.rn.f32x2 %0, %1, %2, %0;" : "+l"(acc) : "l"(a), "l"(b));
}
__device__ __forceinline__ void upk(unsigned long long v, float& x, float& y) {
    asm("mov.b64 {%0,%1}, %2;" : "=f"(x), "=f"(y) : "l"(v));
}
__device__ __forceinline__ unsigned long long pk(float x, float y) {
    unsigned long long r;
    asm("mov.b64 %0, {%1,%2};" : "=l"(r) : "f"(x), "f"(y));
    return r;
}
__device__ __forceinline__ unsigned sptr(const void* p) {
    return (unsigned)__cvta_generic_to_shared(p);
}
__device__ __forceinline__ void lds_v2u64(unsigned addr,
                                          unsigned long long& a,
                                          unsigned long long& b) {
    asm("ld.shared.v2.u64 {%0,%1}, [%2];" : "=l"(a), "=l"(b) : "r"(addr));
}
__device__ __forceinline__ void sts_u64(unsigned addr, unsigned long long v) {
    asm("st.shared.u64 [%0], %1;" :: "r"(addr), "l"(v));
}

// ---------------- K0: fold weights ----------------
__global__ void setup_kernel(const float* __restrict__ w1,
                             const float* __restrict__ w2,
                             const float* __restrict__ w3,
                             const float* __restrict__ b2,
                             const float* __restrict__ b3)
{
    int e = blockIdx.x * 256 + threadIdx.x;
    if (blockIdx.x < 12) {  // 3072 elements
        int j = e / 48, k = e % 48;
        float a = w1[k * 64 + j];
        float b = w1[(48 + k) * 64 + j];
        float c = w1[(96 + k) * 64 + j];
        float d = w1[(144 + k) * 64 + j];
        g_WbcT[j * 48 + k] = b - c;
        g_WacT[j * 48 + k] = a + c;
        g_WdT [j * 48 + k] = d;
    } else {
        int t = threadIdx.x;
        if (t < 64) {
            float v = 0.f;
#pragma unroll
            for (int m = 0; m < 16; m++) v += w2[t * 16 + m] * w3[m];
            g_v[t] = v;
        } else if (t == 64) {
            float cs = b3[0];
#pragma unroll
            for (int m = 0; m < 16; m++) cs += b2[m] * w3[m];
            g_cs[0] = cs;
        }
    }
}

// ---------------- K1: attention, 128 threads per (b,n) ----------------
// lane owns j-pair (2 columns of folded M) register-resident;
// warp w handles a contiguous chunk of l's.
__global__ void __launch_bounds__(128) attn_kernel(
    const float* __restrict__ emb_user,
    const float* __restrict__ emb_item,
    const float* __restrict__ emb_cate,
    const float* __restrict__ b1,
    const int* __restrict__ user,
    const int* __restrict__ items,
    const int* __restrict__ items_cate,
    const int* __restrict__ ii,
    const int* __restrict__ iic)
{
    const int bn   = blockIdx.x;
    const int t    = threadIdx.x;
    const int w    = t >> 5;
    const int lane = t & 31;

    __shared__ __align__(16) float q_s[48];
    __shared__ __align__(16) unsigned long long Mx[24 * 64]; // [kp][j] 12.3KB
    __shared__ float cn_s[64];
    __shared__ float v_s[64];
    __shared__ __align__(16) float he_s[LL][52];             // 10.4KB
    __shared__ float S[LL][33];                               // 6.6KB
    __shared__ float sc_s[LL];
    __shared__ int   idx_s[LL];

    // ---- q + v ----
    if (t < 32)       q_s[t] = emb_item[(size_t)items[bn] * DI + t];
    else if (t < 48)  q_s[t] = emb_cate[(size_t)items_cate[bn] * DC + (t - 32)];
    if (t < 64)       v_s[t] = g_v[t];
    if (t >= 64 && t < 64 + LL) idx_s[t - 64] = ii[bn * LL + (t - 64)];
    __syncthreads();   // q_s ready for fold

    // ---- gather he: 600 float4 chunks over 128 threads ----
#pragma unroll
    for (int idx = t; idx < LL * 12; idx += 128) {
        int row = idx / 12, c = idx % 12;
        if (c < 8) {
            int iidx = __ldg(&ii[bn * LL + row]);
            *(float4*)&he_s[row][c * 4] =
                *(const float4*)(emb_item + (size_t)iidx * DI + c * 4);
        } else {
            int icd = __ldg(&iic[bn * LL + row]);
            *(float4*)&he_s[row][32 + (c - 8) * 4] =
                *(const float4*)(emb_cate + (size_t)icd * DC + (c - 8) * 4);
        }
    }

    // ---- fold (threads < 64): M[j][k] = Wbc + q[k]*Wd, packed into Mx[kp][j]
    if (t < 64) {
        const int j = t;
        float cn = b1[j];
        const float4* wbc = (const float4*)(g_WbcT + j * 48);
        const float4* wac = (const float4*)(g_WacT + j * 48);
        const float4* wd  = (const float4*)(g_WdT  + j * 48);
        const float4* q4  = (const float4*)q_s;
        unsigned mxb = sptr(Mx) + j * 8;
#pragma unroll
        for (int c = 0; c < 12; c++) {
            float4 qb = q4[c];
            float4 fb = wbc[c], fa = wac[c], fd = wd[c];
            float mx = fmaf(qb.x, fd.x, fb.x);
            float my = fmaf(qb.y, fd.y, fb.y);
            float mz = fmaf(qb.z, fd.z, fb.z);
            float mw = fmaf(qb.w, fd.w, fb.w);
            sts_u64(mxb + (2 * c) * 512, pk(mx, my));        // 64 u64 = 512B per kp
            sts_u64(mxb + (2 * c + 1) * 512, pk(mz, mw));
            cn = fmaf(qb.x, fa.x, cn);
            cn = fmaf(qb.y, fa.y, cn);
            cn = fmaf(qb.z, fa.z, cn);
            cn = fmaf(qb.w, fa.w, cn);
        }
        cn_s[j] = cn;
    }
    __syncthreads();   // he_s, Mx, cn_s ready

    // ---- load my j-pair columns into registers ----
    unsigned long long A0[24], A1[24];
    {
        unsigned mb = sptr(Mx) + (2 * lane) * 8;
#pragma unroll
        for (int kp = 0; kp < 24; kp++)
            lds_v2u64(mb + kp * 512, A0[kp], A1[kp]);
    }
    const float cn0 = cn_s[2 * lane], cn1 = cn_s[2 * lane + 1];
    const float v0  = v_s[2 * lane],  v1  = v_s[2 * lane + 1];

    // ---- l loop: warp w covers [l0, l0+cnt) ----
    const int l0  = (w < 2) ? w * 13 : 26 + (w - 2) * 12;
    const int cnt = (w < 2) ? 13 : 12;
    for (int li = 0; li < cnt; li++) {
        const int l = l0 + li;
        unsigned hb = sptr(&he_s[l][0]);
        unsigned long long acc0 = 0ull, acc1 = 0ull;
#pragma unroll
        for (int c = 0; c < 12; c++) {
            unsigned long long h0, h1;
            lds_v2u64(hb + c * 16, h0, h1);
            ffma2(acc0, h0, A0[2 * c]);
            ffma2(acc0, h1, A0[2 * c + 1]);
            ffma2(acc1, h0, A1[2 * c]);
            ffma2(acc1, h1, A1[2 * c + 1]);
        }
        float x0, y0, x1, y1;
        upk(acc0, x0, y0);
        upk(acc1, x1, y1);
        float r0 = fmaxf(x0 + y0 + cn0, 0.f);
        float r1 = fmaxf(x1 + y1 + cn1, 0.f);
        S[l][lane] = fmaf(r0, v0, r1 * v1);
    }
    __syncthreads();

    // ---- reduce scores over 32 lanes (conflict-free: pad 33) ----
    if (t < LL) {
        float s = g_cs[0];
#pragma unroll
        for (int k = 0; k < 32; k++) s += S[t][k];
        sc_s[t] = (idx_s[t] == 0) ? 0.f : s;
    }
    __syncthreads();

    // ---- pooled + feat ----
    float* fo = g_feat + bn * FEAT;
    if (t < 48) {
        float pooled = 0.f;
#pragma unroll 10
        for (int l = 0; l < LL; l++)
            pooled = fmaf(sc_s[l], he_s[l][t], pooled);
        fo[t]      = q_s[t];
        fo[48 + t] = pooled;
    } else if (t < 80) {
        fo[96 + (t - 48)] = emb_user[(size_t)user[bn] * DU + (t - 48)];
    }
}

// ---------------- K2: FC MLP 128->200->80->1 ----------------
#define ROWS 16
__global__ void __launch_bounds__(256) fc_kernel(
    const float* __restrict__ fw1, const float* __restrict__ fb1,
    const float* __restrict__ fw2, const float* __restrict__ fb2,
    const float* __restrict__ fw3, const float* __restrict__ fb3)
{
    const int t = threadIdx.x;
    const int row0 = blockIdx.x * ROWS;

    __shared__ __align__(16) float fs[ROWS][FEAT];
    __shared__ float x1[ROWS][200];
    __shared__ float x2[ROWS][80];

    const float4* src = (const float4*)(g_feat + row0 * FEAT);
    float4* dst = (float4*)&fs[0][0];
    for (int i = t; i < ROWS * FEAT / 4; i += 256) dst[i] = src[i];
    __syncthreads();

    for (int idx = t; idx < ROWS * 200; idx += 256) {
        int r = idx / 200, jj = idx % 200;
        float acc = fb1[jj];
#pragma unroll 8
        for (int i = 0; i < FEAT; i++)
            acc = fmaf(fs[r][i], fw1[i * 200 + jj], acc);
        x1[r][jj] = fmaxf(acc, 0.0f);
    }
    __syncthreads();

    for (int idx = t; idx < ROWS * 80; idx += 256) {
        int r = idx / 80, jj = idx % 80;
        float acc = fb2[jj];
#pragma unroll 8
        for (int i = 0; i < 200; i++)
            acc = fmaf(x1[r][i], fw2[i * 80 + jj], acc);
        x2[r][jj] = fmaxf(acc, 0.0f);
    }
    __syncthreads();

    if (t < ROWS) {
        float acc = fb3[0];
#pragma unroll 8
        for (int i = 0; i < 80; i++)
            acc = fmaf(x2[t][i], fw3[i], acc);
        g_logits[row0 + t] = 1.0f / (1.0f + expf(-acc));
    }
}

// ---------------- K3: masked softmax over N=256 ----------------
__global__ void __launch_bounds__(256) softmax_kernel(
    const int* __restrict__ items, float* __restrict__ out)
{
    const int b = blockIdx.x;
    const int t = threadIdx.x;
    const int wid = t >> 5, lane = t & 31;

    __shared__ float red[8];
    __shared__ float s_mx, s_sum;

    float l = g_logits[b * NN + t];
    bool masked = (items[b * NN + t] == 0);
    float val = masked ? -FLT_MAX : l;

    float mx = val;
#pragma unroll
    for (int o = 16; o > 0; o >>= 1)
        mx = fmaxf(mx, __shfl_down_sync(0xffffffffu, mx, o));
    if (lane == 0) red[wid] = mx;
    __syncthreads();
    if (t == 0) {
        float m = red[0];
#pragma unroll
        for (int w = 1; w < 8; w++) m = fmaxf(m, red[w]);
        s_mx = m;
    }
    __syncthreads();
    float m = s_mx;

    float e = masked ? 0.0f : expf(l - m);
    float sum = e;
#pragma unroll
    for (int o = 16; o > 0; o >>= 1)
        sum += __shfl_down_sync(0xffffffffu, sum, o);
    if (lane == 0) red[wid] = sum;
    __syncthreads();
    if (t == 0) {
        float s = 0.0f;
#pragma unroll
        for (int w = 0; w < 8; w++) s += red[w];
        s_sum = s;
    }
    __syncthreads();

    out[b * NN + t] = e / s_sum;
}

// ---------------- launch ----------------
extern "C" void kernel_launch(void* const* d_in, const int* in_sizes, int n_in,
                              void* d_out, int out_size)
{
    const float* emb_user  = (const float*)d_in[0];
    const float* emb_item  = (const float*)d_in[1];
    const float* emb_cate  = (const float*)d_in[2];
    const float* att_w1    = (const float*)d_in[3];
    const float* att_b1    = (const float*)d_in[4];
    const float* att_w2    = (const float*)d_in[5];
    const float* att_b2    = (const float*)d_in[6];
    const float* att_w3    = (const float*)d_in[7];
    const float* att_b3    = (const float*)d_in[8];
    const float* fc_w1     = (const float*)d_in[9];
    const float* fc_b1     = (const float*)d_in[10];
    const float* fc_w2     = (const float*)d_in[11];
    const float* fc_b2     = (const float*)d_in[12];
    const float* fc_w3     = (const float*)d_in[13];
    const float* fc_b3     = (const float*)d_in[14];
    const int*   user      = (const int*)d_in[15];
    const int*   items     = (const int*)d_in[16];
    const int*   items_cate= (const int*)d_in[17];
    const int*   ii        = (const int*)d_in[18];
    const int*   iic       = (const int*)d_in[19];
    float* out = (float*)d_out;

    setup_kernel<<<13, 256>>>(att_w1, att_w2, att_w3, att_b2, att_b3);
    attn_kernel<<<BN, 128>>>(emb_user, emb_item, emb_cate, att_b1,
                             user, items, items_cate, ii, iic);
    fc_kernel<<<BN / ROWS, 256>>>(fc_w1, fc_b1, fc_w2, fc_b2, fc_w3, fc_b3);
    softmax_kernel<<<BB, 256>>>(items, out);
}

// round 4
// speedup vs baseline: 2.2905x; 1.1638x over previous
#include <cuda_runtime.h>
#include <cuda_bf16.h>
#include <cfloat>
#include <cmath>

#define BB 32
#define NN 256
#define LL 50
#define BN (BB * NN)          // 8192
#define DU 32
#define DI 32
#define DC 16
#define DD 48
#define FEAT 128

// ---------------- scratch (no allocs allowed) ----------------
__device__ float g_feat[BN * FEAT];
__device__ float g_logits[BN];
__device__ __align__(16) float g_WbcT[64 * 48];  // [j][k] = w1b - w1c
__device__ __align__(16) float g_WacT[64 * 48];  // [j][k] = w1a + w1c
__device__ __align__(16) float g_WdT [64 * 48];  // [j][k] = w1d
__device__ float g_v[64];                        // w2 @ w3
__device__ float g_cs[1];                        // b2.w3 + b3

// ---------------- f32x2 helpers (sm_100+) ----------------
__device__ __forceinline__ void ffma2(unsigned long long& acc,
                                      unsigned long long a,
                                      unsigned long long b) {
    asm("fma.rn.f32x2 %0, %1, %2, %0;" : "+l"(acc) : "l"(a), "l"(b));
}
__device__ __forceinline__ void add2(unsigned long long& a, unsigned long long b) {
    asm("add.rn.f32x2 %0, %0, %1;" : "+l"(a) : "l"(b));
}
__device__ __forceinline__ void upk(unsigned long long v, float& x, float& y) {
    asm("mov.b64 {%0,%1}, %2;" : "=f"(x), "=f"(y) : "l"(v));
}
__device__ __forceinline__ unsigned long long pk(float x, float y) {
    unsigned long long r;
    asm("mov.b64 %0, {%1,%2};" : "=l"(r) : "f"(x), "f"(y));
    return r;
}
__device__ __forceinline__ unsigned sptr(const void* p) {
    return (unsigned)__cvta_generic_to_shared(p);
}
__device__ __forceinline__ void lds_v2u64(unsigned addr,
                                          unsigned long long& a,
                                          unsigned long long& b) {
    asm("ld.shared.v2.u64 {%0,%1}, [%2];" : "=l"(a), "=l"(b) : "r"(addr));
}
__device__ __forceinline__ void sts_u64(unsigned addr, unsigned long long v) {
    asm("st.shared.u64 [%0], %1;" :: "r"(addr), "l"(v));
}

// ---------------- K0: fold attention weights ----------------
__global__ void setup_kernel(const float* __restrict__ w1,
                             const float* __restrict__ w2,
                             const float* __restrict__ w3,
                             const float* __restrict__ b2,
                             const float* __restrict__ b3)
{
    int e = blockIdx.x * 256 + threadIdx.x;
    if (blockIdx.x < 12) {
        int j = e / 48, k = e % 48;
        float a = w1[k * 64 + j];
        float b = w1[(48 + k) * 64 + j];
        float c = w1[(96 + k) * 64 + j];
        float d = w1[(144 + k) * 64 + j];
        g_WbcT[j * 48 + k] = b - c;
        g_WacT[j * 48 + k] = a + c;
        g_WdT [j * 48 + k] = d;
    } else {
        int t = threadIdx.x;
        if (t < 64) {
            float v = 0.f;
#pragma unroll
            for (int m = 0; m < 16; m++) v += w2[t * 16 + m] * w3[m];
            g_v[t] = v;
        } else if (t == 64) {
            float cs = b3[0];
#pragma unroll
            for (int m = 0; m < 16; m++) cs += b2[m] * w3[m];
            g_cs[0] = cs;
        }
    }
}

// ---------------- K1: attention ----------------
__global__ void __launch_bounds__(128, 4) attn_kernel(
    const float* __restrict__ emb_user,
    const float* __restrict__ emb_item,
    const float* __restrict__ emb_cate,
    const float* __restrict__ b1,
    const int* __restrict__ user,
    const int* __restrict__ items,
    const int* __restrict__ items_cate,
    const int* __restrict__ ii,
    const int* __restrict__ iic)
{
    const int bn   = blockIdx.x;
    const int t    = threadIdx.x;
    const int w    = t >> 5;
    const int lane = t & 31;

    __shared__ __align__(16) float q_s[48];
    __shared__ __align__(16) unsigned long long Mx[24 * 64]; // [kp][j]
    __shared__ float cn_part[2][64];
    __shared__ float v_s[64];
    __shared__ __align__(16) float he_s[LL][52];
    __shared__ float S[LL][33];
    __shared__ float sc_s[LL];
    __shared__ int   idx_s[LL];
    __shared__ int   iic_s[LL];

    // ---- stage q, v, indices ----
    if (t < 32)       q_s[t] = emb_item[(size_t)items[bn] * DI + t];
    else if (t < 48)  q_s[t] = emb_cate[(size_t)items_cate[bn] * DC + (t - 32)];
    if (t < 64)       v_s[t] = g_v[t];
    if (t >= 64 && t < 64 + LL) idx_s[t - 64] = ii[bn * LL + (t - 64)];
    if (t < LL)       iic_s[t] = iic[bn * LL + t];
    __syncthreads();

    // ---- gather he (600 float4 chunks over 128 threads) ----
    for (int idx = t; idx < LL * 12; idx += 128) {
        int row = idx / 12, c = idx % 12;
        if (c < 8) {
            *(float4*)&he_s[row][c * 4] =
                *(const float4*)(emb_item + (size_t)idx_s[row] * DI + c * 4);
        } else {
            *(float4*)&he_s[row][32 + (c - 8) * 4] =
                *(const float4*)(emb_cate + (size_t)iic_s[row] * DC + (c - 8) * 4);
        }
    }

    // ---- fold over ALL 128 threads: j = t&63, k-half = t>>6 ----
    {
        const int j = t & 63;
        const int half = t >> 6;         // 0: c 0..5, 1: c 6..11
        float cn = (half == 0) ? b1[j] : 0.f;
        const float4* wbc = (const float4*)(g_WbcT + j * 48) + half * 6;
        const float4* wac = (const float4*)(g_WacT + j * 48) + half * 6;
        const float4* wd  = (const float4*)(g_WdT  + j * 48) + half * 6;
        const float4* q4  = (const float4*)q_s + half * 6;
        unsigned mxb = sptr(Mx) + j * 8 + half * 12 * 512;
#pragma unroll
        for (int c = 0; c < 6; c++) {
            float4 qb = q4[c];
            float4 fb = wbc[c], fa = wac[c], fd = wd[c];
            float mx = fmaf(qb.x, fd.x, fb.x);
            float my = fmaf(qb.y, fd.y, fb.y);
            float mz = fmaf(qb.z, fd.z, fb.z);
            float mw = fmaf(qb.w, fd.w, fb.w);
            sts_u64(mxb + (2 * c) * 512, pk(mx, my));
            sts_u64(mxb + (2 * c + 1) * 512, pk(mz, mw));
            cn = fmaf(qb.x, fa.x, cn);
            cn = fmaf(qb.y, fa.y, cn);
            cn = fmaf(qb.z, fa.z, cn);
            cn = fmaf(qb.w, fa.w, cn);
        }
        cn_part[half][j] = cn;
    }
    __syncthreads();

    // ---- register-load my j-pair columns ----
    unsigned long long A0[24], A1[24];
    {
        unsigned mb = sptr(Mx) + (2 * lane) * 8;
#pragma unroll
        for (int kp = 0; kp < 24; kp++)
            lds_v2u64(mb + kp * 512, A0[kp], A1[kp]);
    }
    const float cn0 = cn_part[0][2 * lane] + cn_part[1][2 * lane];
    const float cn1 = cn_part[0][2 * lane + 1] + cn_part[1][2 * lane + 1];
    const float v0  = v_s[2 * lane],  v1 = v_s[2 * lane + 1];

    // ---- l loop: 4 independent accumulator chains ----
    const int l0  = (w < 2) ? w * 13 : 26 + (w - 2) * 12;
    const int cnt = (w < 2) ? 13 : 12;
    for (int li = 0; li < cnt; li++) {
        const int l = l0 + li;
        unsigned hb = sptr(&he_s[l][0]);
        unsigned long long a0a = 0ull, a0b = 0ull, a1a = 0ull, a1b = 0ull;
#pragma unroll
        for (int c = 0; c < 6; c++) {
            unsigned long long h0, h1, h2, h3;
            lds_v2u64(hb + c * 16, h0, h1);
            lds_v2u64(hb + (c + 6) * 16, h2, h3);
            ffma2(a0a, h0, A0[2 * c]);
            ffma2(a0a, h1, A0[2 * c + 1]);
            ffma2(a1a, h0, A1[2 * c]);
            ffma2(a1a, h1, A1[2 * c + 1]);
            ffma2(a0b, h2, A0[2 * c + 12]);
            ffma2(a0b, h3, A0[2 * c + 13]);
            ffma2(a1b, h2, A1[2 * c + 12]);
            ffma2(a1b, h3, A1[2 * c + 13]);
        }
        add2(a0a, a0b);
        add2(a1a, a1b);
        float x0, y0, x1, y1;
        upk(a0a, x0, y0);
        upk(a1a, x1, y1);
        float r0 = fmaxf(x0 + y0 + cn0, 0.f);
        float r1 = fmaxf(x1 + y1 + cn1, 0.f);
        S[l][lane] = fmaf(r0, v0, r1 * v1);
    }
    __syncthreads();

    // ---- reduce scores ----
    if (t < LL) {
        float s = g_cs[0];
#pragma unroll
        for (int k = 0; k < 32; k++) s += S[t][k];
        sc_s[t] = (idx_s[t] == 0) ? 0.f : s;
    }
    __syncthreads();

    // ---- pooled + feat ----
    float* fo = g_feat + bn * FEAT;
    if (t < 48) {
        float pooled = 0.f;
#pragma unroll 10
        for (int l = 0; l < LL; l++)
            pooled = fmaf(sc_s[l], he_s[l][t], pooled);
        fo[t]      = q_s[t];
        fo[48 + t] = pooled;
    } else if (t < 80) {
        fo[96 + (t - 48)] = emb_user[(size_t)user[bn] * DU + (t - 48)];
    }
}

// ---------------- K2: FC MLP, f32x2 register-tiled ----------------
#define ROWS 16
__global__ void __launch_bounds__(256) fc_kernel(
    const float* __restrict__ fw1, const float* __restrict__ fb1,
    const float* __restrict__ fw2, const float* __restrict__ fb2,
    const float* __restrict__ fw3, const float* __restrict__ fb3)
{
    const int t = threadIdx.x;
    const int row0 = blockIdx.x * ROWS;

    __shared__ __align__(16) unsigned long long fsd[ROWS][129]; // dup (x,x)
    __shared__ __align__(16) unsigned long long x1d[ROWS][202]; // dup (h,h)
    __shared__ __align__(16) float x2[ROWS][82];

    // stage feat, duplicated into u64 lanes
    const float4* src = (const float4*)(g_feat + row0 * FEAT);
    for (int i = t; i < ROWS * FEAT / 4; i += 256) {
        float4 v = src[i];
        int r = i >> 5;            // 32 float4 per row
        int c = (i & 31) * 4;
        fsd[r][c]     = pk(v.x, v.x);
        fsd[r][c + 1] = pk(v.y, v.y);
        fsd[r][c + 2] = pk(v.z, v.z);
        fsd[r][c + 3] = pk(v.w, v.w);
    }
    __syncthreads();

    // fc1: 200 threads: jj-pair = t>>1, 8 rows = (t&1)*8
    if (t < 200) {
        const int jjp = t >> 1;
        const int rg  = (t & 1) * 8;
        const unsigned long long* wp = (const unsigned long long*)fw1 + jjp;
        const unsigned long long bias = *(const unsigned long long*)(fb1 + 2 * jjp);
        unsigned long long acc[8];
#pragma unroll
        for (int r = 0; r < 8; r++) acc[r] = bias;
#pragma unroll 4
        for (int i = 0; i < FEAT; i++) {
            unsigned long long wv = wp[i * 100];
#pragma unroll
            for (int r = 0; r < 8; r++)
                ffma2(acc[r], fsd[rg + r][i], wv);
        }
#pragma unroll
        for (int r = 0; r < 8; r++) {
            float h0, h1;
            upk(acc[r], h0, h1);
            h0 = fmaxf(h0, 0.f);
            h1 = fmaxf(h1, 0.f);
            x1d[rg + r][2 * jjp]     = pk(h0, h0);
            x1d[rg + r][2 * jjp + 1] = pk(h1, h1);
        }
    }
    __syncthreads();

    // fc2: 160 threads: jj-pair = t>>2 (40), 4 rows = (t&3)*4
    if (t < 160) {
        const int jjp = t >> 2;
        const int rg  = (t & 3) * 4;
        const unsigned long long* wp = (const unsigned long long*)fw2 + jjp;
        const unsigned long long bias = *(const unsigned long long*)(fb2 + 2 * jjp);
        unsigned long long acc[4];
#pragma unroll
        for (int r = 0; r < 4; r++) acc[r] = bias;
#pragma unroll 4
        for (int i = 0; i < 200; i++) {
            unsigned long long wv = wp[i * 40];
#pragma unroll
            for (int r = 0; r < 4; r++)
                ffma2(acc[r], x1d[rg + r][i], wv);
        }
#pragma unroll
        for (int r = 0; r < 4; r++) {
            float h0, h1;
            upk(acc[r], h0, h1);
            x2[rg + r][2 * jjp]     = fmaxf(h0, 0.f);
            x2[rg + r][2 * jjp + 1] = fmaxf(h1, 0.f);
        }
    }
    __syncthreads();

    // fc3 + sigmoid
    if (t < ROWS) {
        const unsigned long long* wp = (const unsigned long long*)fw3;
        const unsigned long long* xp = (const unsigned long long*)&x2[t][0];
        unsigned long long acc = 0ull;
#pragma unroll
        for (int ip = 0; ip < 40; ip++)
            ffma2(acc, xp[ip], wp[ip]);
        float a, b;
        upk(acc, a, b);
        float s = a + b + fb3[0];
        g_logits[row0 + t] = 1.0f / (1.0f + expf(-s));
    }
}

// ---------------- K3: masked softmax ----------------
__global__ void __launch_bounds__(256) softmax_kernel(
    const int* __restrict__ items, float* __restrict__ out)
{
    const int b = blockIdx.x;
    const int t = threadIdx.x;
    const int wid = t >> 5, lane = t & 31;

    __shared__ float red[8];
    __shared__ float s_mx, s_sum;

    float l = g_logits[b * NN + t];
    bool masked = (items[b * NN + t] == 0);
    float val = masked ? -FLT_MAX : l;

    float mx = val;
#pragma unroll
    for (int o = 16; o > 0; o >>= 1)
        mx = fmaxf(mx, __shfl_down_sync(0xffffffffu, mx, o));
    if (lane == 0) red[wid] = mx;
    __syncthreads();
    if (t == 0) {
        float m = red[0];
#pragma unroll
        for (int w = 1; w < 8; w++) m = fmaxf(m, red[w]);
        s_mx = m;
    }
    __syncthreads();
    float m = s_mx;

    float e = masked ? 0.0f : expf(l - m);
    float sum = e;
#pragma unroll
    for (int o = 16; o > 0; o >>= 1)
        sum += __shfl_down_sync(0xffffffffu, sum, o);
    if (lane == 0) red[wid] = sum;
    __syncthreads();
    if (t == 0) {
        float s = 0.0f;
#pragma unroll
        for (int w = 0; w < 8; w++) s += red[w];
        s_sum = s;
    }
    __syncthreads();

    out[b * NN + t] = e / s_sum;
}

// ---------------- launch ----------------
extern "C" void kernel_launch(void* const* d_in, const int* in_sizes, int n_in,
                              void* d_out, int out_size)
{
    const float* emb_user  = (const float*)d_in[0];
    const float* emb_item  = (const float*)d_in[1];
    const float* emb_cate  = (const float*)d_in[2];
    const float* att_w1    = (const float*)d_in[3];
    const float* att_b1    = (const float*)d_in[4];
    const float* att_w2    = (const float*)d_in[5];
    const float* att_b2    = (const float*)d_in[6];
    const float* att_w3    = (const float*)d_in[7];
    const float* att_b3    = (const float*)d_in[8];
    const float* fc_w1     = (const float*)d_in[9];
    const float* fc_b1     = (const float*)d_in[10];
    const float* fc_w2     = (const float*)d_in[11];
    const float* fc_b2     = (const float*)d_in[12];
    const float* fc_w3     = (const float*)d_in[13];
    const float* fc_b3     = (const float*)d_in[14];
    const int*   user      = (const int*)d_in[15];
    const int*   items     = (const int*)d_in[16];
    const int*   items_cate= (const int*)d_in[17];
    const int*   ii        = (const int*)d_in[18];
    const int*   iic       = (const int*)d_in[19];
    float* out = (float*)d_out;

    setup_kernel<<<13, 256>>>(att_w1, att_w2, att_w3, att_b2, att_b3);
    attn_kernel<<<BN, 128>>>(emb_user, emb_item, emb_cate, att_b1,
                             user, items, items_cate, ii, iic);
    fc_kernel<<<BN / ROWS, 256>>>(fc_w1, fc_b1, fc_w2, fc_b2, fc_w3, fc_b3);
    softmax_kernel<<<BB, 256>>>(items, out);
}

// round 5
// speedup vs baseline: 2.7308x; 1.1922x over previous
#include <cuda_runtime.h>
#include <cuda_bf16.h>
#include <cfloat>
#include <cmath>

#define BB 32
#define NN 256
#define LL 50
#define BN (BB * NN)          // 8192
#define DU 32
#define DI 32
#define DC 16
#define DD 48
#define FEAT 128

// ---------------- scratch (no allocs allowed) ----------------
__device__ float g_feat[BN * FEAT];
__device__ float g_logits[BN];
__device__ __align__(16) float g_WbcT[64 * 48];  // [j][k] = w1b - w1c
__device__ __align__(16) float g_WacT[64 * 48];  // [j][k] = w1a + w1c
__device__ __align__(16) float g_WdT [64 * 48];  // [j][k] = w1d
__device__ float g_v[64];                        // w2 @ w3
__device__ float g_cs[1];                        // b2.w3 + b3

// ---------------- helpers ----------------
__device__ __forceinline__ void ffma2(unsigned long long& acc,
                                      unsigned long long a,
                                      unsigned long long b) {
    asm("fma.rn.f32x2 %0, %1, %2, %0;" : "+l"(acc) : "l"(a), "l"(b));
}
__device__ __forceinline__ void add2(unsigned long long& a, unsigned long long b) {
    asm("add.rn.f32x2 %0, %0, %1;" : "+l"(a) : "l"(b));
}
__device__ __forceinline__ void upk(unsigned long long v, float& x, float& y) {
    asm("mov.b64 {%0,%1}, %2;" : "=f"(x), "=f"(y) : "l"(v));
}
__device__ __forceinline__ unsigned long long pk(float x, float y) {
    unsigned long long r;
    asm("mov.b64 %0, {%1,%2};" : "=l"(r) : "f"(x), "f"(y));
    return r;
}
__device__ __forceinline__ unsigned sptr(const void* p) {
    return (unsigned)__cvta_generic_to_shared(p);
}
__device__ __forceinline__ void lds_v2u64(unsigned addr,
                                          unsigned long long& a,
                                          unsigned long long& b) {
    asm("ld.shared.v2.u64 {%0,%1}, [%2];" : "=l"(a), "=l"(b) : "r"(addr));
}
__device__ __forceinline__ void sts_u64(unsigned addr, unsigned long long v) {
    asm("st.shared.u64 [%0], %1;" :: "r"(addr), "l"(v));
}
__device__ __forceinline__ void cpasync16(unsigned dst, const void* src) {
    asm volatile("cp.async.ca.shared.global [%0], [%1], 16;"
                 :: "r"(dst), "l"(src));
}
__device__ __forceinline__ void cpasync_wait_all() {
    asm volatile("cp.async.commit_group;\ncp.async.wait_group 0;" ::: "memory");
}

// ---------------- K0: fold attention weights ----------------
__global__ void setup_kernel(const float* __restrict__ w1,
                             const float* __restrict__ w2,
                             const float* __restrict__ w3,
                             const float* __restrict__ b2,
                             const float* __restrict__ b3)
{
    int e = blockIdx.x * 256 + threadIdx.x;
    if (blockIdx.x < 12) {
        int j = e / 48, k = e % 48;
        float a = w1[k * 64 + j];
        float b = w1[(48 + k) * 64 + j];
        float c = w1[(96 + k) * 64 + j];
        float d = w1[(144 + k) * 64 + j];
        g_WbcT[j * 48 + k] = b - c;
        g_WacT[j * 48 + k] = a + c;
        g_WdT [j * 48 + k] = d;
    } else {
        int t = threadIdx.x;
        if (t < 64) {
            float v = 0.f;
#pragma unroll
            for (int m = 0; m < 16; m++) v += w2[t * 16 + m] * w3[m];
            g_v[t] = v;
        } else if (t == 64) {
            float cs = b3[0];
#pragma unroll
            for (int m = 0; m < 16; m++) cs += b2[m] * w3[m];
            g_cs[0] = cs;
        }
    }
}

// ---------------- K1: attention ----------------
__global__ void __launch_bounds__(128, 4) attn_kernel(
    const float* __restrict__ emb_user,
    const float* __restrict__ emb_item,
    const float* __restrict__ emb_cate,
    const float* __restrict__ b1,
    const int* __restrict__ user,
    const int* __restrict__ items,
    const int* __restrict__ items_cate,
    const int* __restrict__ ii,
    const int* __restrict__ iic)
{
    const int bn   = blockIdx.x;
    const int t    = threadIdx.x;
    const int w    = t >> 5;
    const int lane = t & 31;

    __shared__ __align__(16) float q_s[48];
    __shared__ __align__(16) unsigned long long Mx[24 * 64]; // [kp][j]
    __shared__ float cn_part[2][64];
    __shared__ float v_s[64];
    __shared__ __align__(16) float he_s[LL][52];
    __shared__ float S[LL][33];
    __shared__ float sc_s[LL];
    __shared__ int   idx_s[LL];

    // ================= phase 1 (no barrier until cp.async wait) ===========
    // (a) issue he gathers via cp.async; each thread fetches its own indices
    {
        const unsigned heb = sptr(he_s);
#pragma unroll
        for (int u = 0; u < 5; u++) {
            int idx = t + u * 128;
            if (idx < LL * 12) {
                int row = idx / 12, c = idx % 12;
                const float* src;
                if (c < 8) {
                    int e = __ldg(&ii[bn * LL + row]);
                    src = emb_item + (size_t)e * DI + c * 4;
                } else {
                    int e = __ldg(&iic[bn * LL + row]);
                    src = emb_cate + (size_t)e * DC + (c - 8) * 4;
                }
                cpasync16(heb + row * 208 + c * 16, src);
            }
        }
    }

    // (b) stage q (for feat output), v, mask indices
    {
        const int it = __ldg(&items[bn]);
        const int ic = __ldg(&items_cate[bn]);
        if (t < 32)       q_s[t] = __ldg(&emb_item[(size_t)it * DI + t]);
        else if (t < 48)  q_s[t] = __ldg(&emb_cate[(size_t)ic * DC + (t - 32)]);
        if (t < 64)       v_s[t] = g_v[t];
        if (t >= 64 && t < 64 + LL) idx_s[t - 64] = __ldg(&ii[bn * LL + (t - 64)]);
    }

    // (c) fold: j = t&63, k-half = t>>6; q read straight from global (L1 bcast)
    {
        const int j = t & 63;
        const int half = t >> 6;
        const int it = __ldg(&items[bn]);
        const int ic = __ldg(&items_cate[bn]);
        float cn = (half == 0) ? b1[j] : 0.f;
        const float4* wbc = (const float4*)(g_WbcT + j * 48) + half * 6;
        const float4* wac = (const float4*)(g_WacT + j * 48) + half * 6;
        const float4* wd  = (const float4*)(g_WdT  + j * 48) + half * 6;
        unsigned mxb = sptr(Mx) + j * 8 + half * 12 * 512;
#pragma unroll
        for (int c = 0; c < 6; c++) {
            int k4 = half * 24 + c * 4;     // element offset of this float4
            float4 qb;
            if (k4 < 32) qb = *(const float4*)(emb_item + (size_t)it * DI + k4);
            else         qb = *(const float4*)(emb_cate + (size_t)ic * DC + (k4 - 32));
            float4 fb = wbc[c], fa = wac[c], fd = wd[c];
            float mx = fmaf(qb.x, fd.x, fb.x);
            float my = fmaf(qb.y, fd.y, fb.y);
            float mz = fmaf(qb.z, fd.z, fb.z);
            float mw = fmaf(qb.w, fd.w, fb.w);
            sts_u64(mxb + (2 * c) * 512, pk(mx, my));
            sts_u64(mxb + (2 * c + 1) * 512, pk(mz, mw));
            cn = fmaf(qb.x, fa.x, cn);
            cn = fmaf(qb.y, fa.y, cn);
            cn = fmaf(qb.z, fa.z, cn);
            cn = fmaf(qb.w, fa.w, cn);
        }
        cn_part[half][j] = cn;
    }
    cpasync_wait_all();
    __syncthreads();                         // he_s, Mx, cn_part, v_s, idx_s ready

    // ================= phase 2: score ======================================
    unsigned long long A0[24], A1[24];
    {
        unsigned mb = sptr(Mx) + (2 * lane) * 8;
#pragma unroll
        for (int kp = 0; kp < 24; kp++)
            lds_v2u64(mb + kp * 512, A0[kp], A1[kp]);
    }
    const float cn0 = cn_part[0][2 * lane] + cn_part[1][2 * lane];
    const float cn1 = cn_part[0][2 * lane + 1] + cn_part[1][2 * lane + 1];
    const float v0  = v_s[2 * lane],  v1 = v_s[2 * lane + 1];

    const int l0  = (w < 2) ? w * 13 : 26 + (w - 2) * 12;
    const int cnt = (w < 2) ? 13 : 12;
    for (int li = 0; li < cnt; li++) {
        const int l = l0 + li;
        unsigned hb = sptr(&he_s[l][0]);
        unsigned long long a0a = 0ull, a0b = 0ull, a1a = 0ull, a1b = 0ull;
#pragma unroll
        for (int c = 0; c < 6; c++) {
            unsigned long long h0, h1, h2, h3;
            lds_v2u64(hb + c * 16, h0, h1);
            lds_v2u64(hb + (c + 6) * 16, h2, h3);
            ffma2(a0a, h0, A0[2 * c]);
            ffma2(a0a, h1, A0[2 * c + 1]);
            ffma2(a1a, h0, A1[2 * c]);
            ffma2(a1a, h1, A1[2 * c + 1]);
            ffma2(a0b, h2, A0[2 * c + 12]);
            ffma2(a0b, h3, A0[2 * c + 13]);
            ffma2(a1b, h2, A1[2 * c + 12]);
            ffma2(a1b, h3, A1[2 * c + 13]);
        }
        add2(a0a, a0b);
        add2(a1a, a1b);
        float x0, y0, x1, y1;
        upk(a0a, x0, y0);
        upk(a1a, x1, y1);
        float r0 = fmaxf(x0 + y0 + cn0, 0.f);
        float r1 = fmaxf(x1 + y1 + cn1, 0.f);
        S[l][lane] = fmaf(r0, v0, r1 * v1);
    }
    __syncthreads();

    // ================= phase 3: score reduce ===============================
    if (t < LL) {
        float s = g_cs[0];
#pragma unroll
        for (int k = 0; k < 32; k++) s += S[t][k];
        sc_s[t] = (idx_s[t] == 0) ? 0.f : s;
    }
    __syncthreads();

    // ================= phase 4: pooled + feat ==============================
    float* fo = g_feat + bn * FEAT;
    if (t < 48) {
        float pooled = 0.f;
#pragma unroll 10
        for (int l = 0; l < LL; l++)
            pooled = fmaf(sc_s[l], he_s[l][t], pooled);
        fo[t]      = q_s[t];
        fo[48 + t] = pooled;
    } else if (t < 80) {
        fo[96 + (t - 48)] = __ldg(&emb_user[(size_t)__ldg(&user[bn]) * DU + (t - 48)]);
    }
}

// ---------------- K2: FC MLP, f32x2 register-tiled ----------------
#define ROWS 16
__global__ void __launch_bounds__(256) fc_kernel(
    const float* __restrict__ fw1, const float* __restrict__ fb1,
    const float* __restrict__ fw2, const float* __restrict__ fb2,
    const float* __restrict__ fw3, const float* __restrict__ fb3)
{
    const int t = threadIdx.x;
    const int row0 = blockIdx.x * ROWS;

    __shared__ __align__(16) unsigned long long fsd[ROWS][129]; // dup (x,x)
    __shared__ __align__(16) unsigned long long x1d[ROWS][202]; // dup (h,h)
    __shared__ __align__(16) float x2[ROWS][82];

    const float4* src = (const float4*)(g_feat + row0 * FEAT);
    for (int i = t; i < ROWS * FEAT / 4; i += 256) {
        float4 v = src[i];
        int r = i >> 5;
        int c = (i & 31) * 4;
        fsd[r][c]     = pk(v.x, v.x);
        fsd[r][c + 1] = pk(v.y, v.y);
        fsd[r][c + 2] = pk(v.z, v.z);
        fsd[r][c + 3] = pk(v.w, v.w);
    }
    __syncthreads();

    // fc1: 200 threads: jjp = t%100 (coalesced), rows 8 per group
    if (t < 200) {
        const int jjp = t % 100;
        const int rg  = (t / 100) * 8;
        const unsigned long long* wp = (const unsigned long long*)fw1 + jjp;
        const unsigned long long bias = __ldg((const unsigned long long*)(fb1 + 2 * jjp));
        unsigned long long acc[8];
#pragma unroll
        for (int r = 0; r < 8; r++) acc[r] = bias;
#pragma unroll 4
        for (int i = 0; i < FEAT; i++) {
            unsigned long long wv = __ldg(&wp[i * 100]);
#pragma unroll
            for (int r = 0; r < 8; r++)
                ffma2(acc[r], fsd[rg + r][i], wv);
        }
#pragma unroll
        for (int r = 0; r < 8; r++) {
            float h0, h1;
            upk(acc[r], h0, h1);
            h0 = fmaxf(h0, 0.f);
            h1 = fmaxf(h1, 0.f);
            x1d[rg + r][2 * jjp]     = pk(h0, h0);
            x1d[rg + r][2 * jjp + 1] = pk(h1, h1);
        }
    }
    __syncthreads();

    // fc2: 160 threads: jjp = t%40 (coalesced), rows 4 per group
    if (t < 160) {
        const int jjp = t % 40;
        const int rg  = (t / 40) * 4;
        const unsigned long long* wp = (const unsigned long long*)fw2 + jjp;
        const unsigned long long bias = __ldg((const unsigned long long*)(fb2 + 2 * jjp));
        unsigned long long acc[4];
#pragma unroll
        for (int r = 0; r < 4; r++) acc[r] = bias;
#pragma unroll 4
        for (int i = 0; i < 200; i++) {
            unsigned long long wv = __ldg(&wp[i * 40]);
#pragma unroll
            for (int r = 0; r < 4; r++)
                ffma2(acc[r], x1d[rg + r][i], wv);
        }
#pragma unroll
        for (int r = 0; r < 4; r++) {
            float h0, h1;
            upk(acc[r], h0, h1);
            x2[rg + r][2 * jjp]     = fmaxf(h0, 0.f);
            x2[rg + r][2 * jjp + 1] = fmaxf(h1, 0.f);
        }
    }
    __syncthreads();

    // fc3 + sigmoid
    if (t < ROWS) {
        const unsigned long long* wp = (const unsigned long long*)fw3;
        const unsigned long long* xp = (const unsigned long long*)&x2[t][0];
        unsigned long long acc = 0ull;
#pragma unroll
        for (int ip = 0; ip < 40; ip++)
            ffma2(acc, xp[ip], __ldg(&wp[ip]));
        float a, b;
        upk(acc, a, b);
        float s = a + b + fb3[0];
        g_logits[row0 + t] = 1.0f / (1.0f + expf(-s));
    }
}

// ---------------- K3: masked softmax ----------------
__global__ void __launch_bounds__(256) softmax_kernel(
    const int* __restrict__ items, float* __restrict__ out)
{
    const int b = blockIdx.x;
    const int t = threadIdx.x;
    const int wid = t >> 5, lane = t & 31;

    __shared__ float red[8];
    __shared__ float s_mx, s_sum;

    float l = g_logits[b * NN + t];
    bool masked = (items[b * NN + t] == 0);
    float val = masked ? -FLT_MAX : l;

    float mx = val;
#pragma unroll
    for (int o = 16; o > 0; o >>= 1)
        mx = fmaxf(mx, __shfl_down_sync(0xffffffffu, mx, o));
    if (lane == 0) red[wid] = mx;
    __syncthreads();
    if (t == 0) {
        float m = red[0];
#pragma unroll
        for (int w = 1; w < 8; w++) m = fmaxf(m, red[w]);
        s_mx = m;
    }
    __syncthreads();
    float m = s_mx;

    float e = masked ? 0.0f : expf(l - m);
    float sum = e;
#pragma unroll
    for (int o = 16; o > 0; o >>= 1)
        sum += __shfl_down_sync(0xffffffffu, sum, o);
    if (lane == 0) red[wid] = sum;
    __syncthreads();
    if (t == 0) {
        float s = 0.0f;
#pragma unroll
        for (int w = 0; w < 8; w++) s += red[w];
        s_sum = s;
    }
    __syncthreads();

    out[b * NN + t] = e / s_sum;
}

// ---------------- launch ----------------
extern "C" void kernel_launch(void* const* d_in, const int* in_sizes, int n_in,
                              void* d_out, int out_size)
{
    const float* emb_user  = (const float*)d_in[0];
    const float* emb_item  = (const float*)d_in[1];
    const float* emb_cate  = (const float*)d_in[2];
    const float* att_w1    = (const float*)d_in[3];
    const float* att_b1    = (const float*)d_in[4];
    const float* att_w2    = (const float*)d_in[5];
    const float* att_b2    = (const float*)d_in[6];
    const float* att_w3    = (const float*)d_in[7];
    const float* att_b3    = (const float*)d_in[8];
    const float* fc_w1     = (const float*)d_in[9];
    const float* fc_b1     = (const float*)d_in[10];
    const float* fc_w2     = (const float*)d_in[11];
    const float* fc_b2     = (const float*)d_in[12];
    const float* fc_w3     = (const float*)d_in[13];
    const float* fc_b3     = (const float*)d_in[14];
    const int*   user      = (const int*)d_in[15];
    const int*   items     = (const int*)d_in[16];
    const int*   items_cate= (const int*)d_in[17];
    const int*   ii        = (const int*)d_in[18];
    const int*   iic       = (const int*)d_in[19];
    float* out = (float*)d_out;

    setup_kernel<<<13, 256>>>(att_w1, att_w2, att_w3, att_b2, att_b3);
    attn_kernel<<<BN, 128>>>(emb_user, emb_item, emb_cate, att_b1,
                             user, items, items_cate, ii, iic);
    fc_kernel<<<BN / ROWS, 256>>>(fc_w1, fc_b1, fc_w2, fc_b2, fc_w3, fc_b3);
    softmax_kernel<<<BB, 256>>>(items, out);
}

// round 6
// speedup vs baseline: 2.7538x; 1.0084x over previous
#include <cuda_runtime.h>
#include <cuda_bf16.h>
#include <cfloat>
#include <cmath>

#define BB 32
#define NN 256
#define LL 50
#define BN (BB * NN)          // 8192
#define DU 32
#define DI 32
#define DC 16
#define DD 48
#define FEAT 128

// ---------------- scratch (no allocs allowed) ----------------
__device__ float g_feat[BN * FEAT];
__device__ float g_logits[BN];
__device__ __align__(16) float g_WbcT[64 * 48];  // [j][k] = w1b - w1c
__device__ __align__(16) float g_WacT[64 * 48];  // [j][k] = w1a + w1c
__device__ __align__(16) float g_WdT [64 * 48];  // [j][k] = w1d
__device__ float g_v[64];                        // w2 @ w3
__device__ float g_cs[1];                        // b2.w3 + b3

// ---------------- helpers ----------------
__device__ __forceinline__ void ffma2(unsigned long long& acc,
                                      unsigned long long a,
                                      unsigned long long b) {
    asm("fma.rn.f32x2 %0, %1, %2, %0;" : "+l"(acc) : "l"(a), "l"(b));
}
__device__ __forceinline__ void add2(unsigned long long& a, unsigned long long b) {
    asm("add.rn.f32x2 %0, %0, %1;" : "+l"(a) : "l"(b));
}
__device__ __forceinline__ void upk(unsigned long long v, float& x, float& y) {
    asm("mov.b64 {%0,%1}, %2;" : "=f"(x), "=f"(y) : "l"(v));
}
__device__ __forceinline__ unsigned long long pk(float x, float y) {
    unsigned long long r;
    asm("mov.b64 %0, {%1,%2};" : "=l"(r) : "f"(x), "f"(y));
    return r;
}
__device__ __forceinline__ unsigned sptr(const void* p) {
    return (unsigned)__cvta_generic_to_shared(p);
}
__device__ __forceinline__ void lds_v2u64(unsigned addr,
                                          unsigned long long& a,
                                          unsigned long long& b) {
    asm("ld.shared.v2.u64 {%0,%1}, [%2];" : "=l"(a), "=l"(b) : "r"(addr));
}
__device__ __forceinline__ void sts_u64(unsigned addr, unsigned long long v) {
    asm("st.shared.u64 [%0], %1;" :: "r"(addr), "l"(v));
}
__device__ __forceinline__ void cpasync16(unsigned dst, const void* src) {
    asm volatile("cp.async.ca.shared.global [%0], [%1], 16;"
                 :: "r"(dst), "l"(src));
}
__device__ __forceinline__ void cpasync_wait_all() {
    asm volatile("cp.async.commit_group;\ncp.async.wait_group 0;" ::: "memory");
}

// ---------------- K0: fold attention weights ----------------
__global__ void setup_kernel(const float* __restrict__ w1,
                             const float* __restrict__ w2,
                             const float* __restrict__ w3,
                             const float* __restrict__ b2,
                             const float* __restrict__ b3)
{
    int e = blockIdx.x * 256 + threadIdx.x;
    if (blockIdx.x < 12) {
        int j = e / 48, k = e % 48;
        float a = w1[k * 64 + j];
        float b = w1[(48 + k) * 64 + j];
        float c = w1[(96 + k) * 64 + j];
        float d = w1[(144 + k) * 64 + j];
        g_WbcT[j * 48 + k] = b - c;
        g_WacT[j * 48 + k] = a + c;
        g_WdT [j * 48 + k] = d;
    } else {
        int t = threadIdx.x;
        if (t < 64) {
            float v = 0.f;
#pragma unroll
            for (int m = 0; m < 16; m++) v += w2[t * 16 + m] * w3[m];
            g_v[t] = v;
        } else if (t == 64) {
            float cs = b3[0];
#pragma unroll
            for (int m = 0; m < 16; m++) cs += b2[m] * w3[m];
            g_cs[0] = cs;
        }
    }
}

// ---------------- K1: attention ----------------
// 128 threads. Score layout: warp w -> (l-chunk = w>>1, j-half = w&1).
// lane -> (j-pair jp = (lane&15)+16*(w&1), k-half = lane>>4).
// A-tile = 2 cols x 24 k = 48 regs -> 6 CTAs/SM (RF-bound was 4).
__global__ void __launch_bounds__(128, 6) attn_kernel(
    const float* __restrict__ emb_user,
    const float* __restrict__ emb_item,
    const float* __restrict__ emb_cate,
    const float* __restrict__ b1,
    const int* __restrict__ user,
    const int* __restrict__ items,
    const int* __restrict__ items_cate,
    const int* __restrict__ ii,
    const int* __restrict__ iic)
{
    const int bn    = blockIdx.x;
    const int t     = threadIdx.x;
    const int w     = t >> 5;
    const int lane  = t & 31;
    const int khalf = lane >> 4;
    const int jp    = (lane & 15) + 16 * (w & 1);

    __shared__ __align__(16) float q_s[48];
    __shared__ __align__(16) unsigned long long Mx[24 * 64]; // [kp][j]
    __shared__ float cn_part[2][64];
    __shared__ float v_s[64];
    __shared__ __align__(16) float he_s[LL][52];
    __shared__ float S[LL][33];
    __shared__ float sc_s[LL];
    __shared__ int   idx_s[LL];

    // ================= phase 1 (no barrier until cp.async wait) ===========
    // (a) he gathers via cp.async, each thread fetches its own indices
    {
        const unsigned heb = sptr(he_s);
#pragma unroll
        for (int u = 0; u < 5; u++) {
            int idx = t + u * 128;
            if (idx < LL * 12) {
                int row = idx / 12, c = idx % 12;
                const float* src;
                if (c < 8) {
                    int e = __ldg(&ii[bn * LL + row]);
                    src = emb_item + (size_t)e * DI + c * 4;
                } else {
                    int e = __ldg(&iic[bn * LL + row]);
                    src = emb_cate + (size_t)e * DC + (c - 8) * 4;
                }
                cpasync16(heb + row * 208 + c * 16, src);
            }
        }
    }

    // (b) stage q, v, mask indices
    {
        const int it = __ldg(&items[bn]);
        const int ic = __ldg(&items_cate[bn]);
        if (t < 32)       q_s[t] = __ldg(&emb_item[(size_t)it * DI + t]);
        else if (t < 48)  q_s[t] = __ldg(&emb_cate[(size_t)ic * DC + (t - 32)]);
        if (t < 64)       v_s[t] = g_v[t];
        if (t >= 64 && t < 64 + LL) idx_s[t - 64] = __ldg(&ii[bn * LL + (t - 64)]);
    }

    // (c) fold: j = t&63, k-half = t>>6; q read straight from global
    {
        const int j = t & 63;
        const int half = t >> 6;
        const int it = __ldg(&items[bn]);
        const int ic = __ldg(&items_cate[bn]);
        float cn = (half == 0) ? b1[j] : 0.f;
        const float4* wbc = (const float4*)(g_WbcT + j * 48) + half * 6;
        const float4* wac = (const float4*)(g_WacT + j * 48) + half * 6;
        const float4* wd  = (const float4*)(g_WdT  + j * 48) + half * 6;
        unsigned mxb = sptr(Mx) + j * 8 + half * 12 * 512;
#pragma unroll
        for (int c = 0; c < 6; c++) {
            int k4 = half * 24 + c * 4;
            float4 qb;
            if (k4 < 32) qb = *(const float4*)(emb_item + (size_t)it * DI + k4);
            else         qb = *(const float4*)(emb_cate + (size_t)ic * DC + (k4 - 32));
            float4 fb = wbc[c], fa = wac[c], fd = wd[c];
            float mx = fmaf(qb.x, fd.x, fb.x);
            float my = fmaf(qb.y, fd.y, fb.y);
            float mz = fmaf(qb.z, fd.z, fb.z);
            float mw = fmaf(qb.w, fd.w, fb.w);
            sts_u64(mxb + (2 * c) * 512, pk(mx, my));
            sts_u64(mxb + (2 * c + 1) * 512, pk(mz, mw));
            cn = fmaf(qb.x, fa.x, cn);
            cn = fmaf(qb.y, fa.y, cn);
            cn = fmaf(qb.z, fa.z, cn);
            cn = fmaf(qb.w, fa.w, cn);
        }
        cn_part[half][j] = cn;
    }
    cpasync_wait_all();
    __syncthreads();

    // ================= phase 2: score ======================================
    // A-tile: my 2 columns (j = 2jp, 2jp+1), my 24 k values.
    unsigned long long A0[12], A1[12];
    {
        unsigned mb = sptr(Mx) + (2 * jp) * 8 + khalf * 12 * 512;
#pragma unroll
        for (int i = 0; i < 12; i++)
            lds_v2u64(mb + i * 512, A0[i], A1[i]);
    }
    const float cn0 = cn_part[0][2 * jp] + cn_part[1][2 * jp];
    const float cn1 = cn_part[0][2 * jp + 1] + cn_part[1][2 * jp + 1];
    const float v0  = v_s[2 * jp],  v1 = v_s[2 * jp + 1];

    const int l0 = (w >> 1) * 25;
    for (int li = 0; li < 25; li++) {
        const int l = l0 + li;
        unsigned hb = sptr(&he_s[l][0]) + khalf * 96;
        unsigned long long a0a = 0ull, a0b = 0ull, a1a = 0ull, a1b = 0ull;
#pragma unroll
        for (int c = 0; c < 3; c++) {
            unsigned long long h0, h1, h2, h3;
            lds_v2u64(hb + c * 32, h0, h1);
            lds_v2u64(hb + c * 32 + 16, h2, h3);
            ffma2(a0a, h0, A0[4 * c]);
            ffma2(a0a, h1, A0[4 * c + 1]);
            ffma2(a1a, h0, A1[4 * c]);
            ffma2(a1a, h1, A1[4 * c + 1]);
            ffma2(a0b, h2, A0[4 * c + 2]);
            ffma2(a0b, h3, A0[4 * c + 3]);
            ffma2(a1b, h2, A1[4 * c + 2]);
            ffma2(a1b, h3, A1[4 * c + 3]);
        }
        add2(a0a, a0b);
        add2(a1a, a1b);
        float x0, y0, x1, y1;
        upk(a0a, x0, y0);
        upk(a1a, x1, y1);
        float p0 = x0 + y0;
        float p1 = x1 + y1;
        // merge k-halves across half-warps
        p0 += __shfl_xor_sync(0xffffffffu, p0, 16);
        p1 += __shfl_xor_sync(0xffffffffu, p1, 16);
        float r0 = fmaxf(p0 + cn0, 0.f);
        float r1 = fmaxf(p1 + cn1, 0.f);
        if (khalf == 0)
            S[l][jp] = fmaf(r0, v0, r1 * v1);
    }
    __syncthreads();

    // ================= phase 3: score reduce ===============================
    if (t < LL) {
        float s = g_cs[0];
#pragma unroll
        for (int k = 0; k < 32; k++) s += S[t][k];
        sc_s[t] = (idx_s[t] == 0) ? 0.f : s;
    }
    __syncthreads();

    // ================= phase 4: pooled + feat ==============================
    float* fo = g_feat + bn * FEAT;
    if (t < 48) {
        float pooled = 0.f;
#pragma unroll 10
        for (int l = 0; l < LL; l++)
            pooled = fmaf(sc_s[l], he_s[l][t], pooled);
        fo[t]      = q_s[t];
        fo[48 + t] = pooled;
    } else if (t < 80) {
        fo[96 + (t - 48)] = __ldg(&emb_user[(size_t)__ldg(&user[bn]) * DU + (t - 48)]);
    }
}

// ---------------- K2: FC MLP, f32x2 register-tiled ----------------
#define ROWS 16
__global__ void __launch_bounds__(256) fc_kernel(
    const float* __restrict__ fw1, const float* __restrict__ fb1,
    const float* __restrict__ fw2, const float* __restrict__ fb2,
    const float* __restrict__ fw3, const float* __restrict__ fb3)
{
    const int t = threadIdx.x;
    const int row0 = blockIdx.x * ROWS;

    __shared__ __align__(16) unsigned long long fsd[ROWS][129]; // dup (x,x)
    __shared__ __align__(16) unsigned long long x1d[ROWS][202]; // dup (h,h)
    __shared__ __align__(16) float x2[ROWS][82];

    const float4* src = (const float4*)(g_feat + row0 * FEAT);
    for (int i = t; i < ROWS * FEAT / 4; i += 256) {
        float4 v = src[i];
        int r = i >> 5;
        int c = (i & 31) * 4;
        fsd[r][c]     = pk(v.x, v.x);
        fsd[r][c + 1] = pk(v.y, v.y);
        fsd[r][c + 2] = pk(v.z, v.z);
        fsd[r][c + 3] = pk(v.w, v.w);
    }
    __syncthreads();

    if (t < 200) {
        const int jjp = t % 100;
        const int rg  = (t / 100) * 8;
        const unsigned long long* wp = (const unsigned long long*)fw1 + jjp;
        const unsigned long long bias = __ldg((const unsigned long long*)(fb1 + 2 * jjp));
        unsigned long long acc[8];
#pragma unroll
        for (int r = 0; r < 8; r++) acc[r] = bias;
#pragma unroll 4
        for (int i = 0; i < FEAT; i++) {
            unsigned long long wv = __ldg(&wp[i * 100]);
#pragma unroll
            for (int r = 0; r < 8; r++)
                ffma2(acc[r], fsd[rg + r][i], wv);
        }
#pragma unroll
        for (int r = 0; r < 8; r++) {
            float h0, h1;
            upk(acc[r], h0, h1);
            h0 = fmaxf(h0, 0.f);
            h1 = fmaxf(h1, 0.f);
            x1d[rg + r][2 * jjp]     = pk(h0, h0);
            x1d[rg + r][2 * jjp + 1] = pk(h1, h1);
        }
    }
    __syncthreads();

    if (t < 160) {
        const int jjp = t % 40;
        const int rg  = (t / 40) * 4;
        const unsigned long long* wp = (const unsigned long long*)fw2 + jjp;
        const unsigned long long bias = __ldg((const unsigned long long*)(fb2 + 2 * jjp));
        unsigned long long acc[4];
#pragma unroll
        for (int r = 0; r < 4; r++) acc[r] = bias;
#pragma unroll 4
        for (int i = 0; i < 200; i++) {
            unsigned long long wv = __ldg(&wp[i * 40]);
#pragma unroll
            for (int r = 0; r < 4; r++)
                ffma2(acc[r], x1d[rg + r][i], wv);
        }
#pragma unroll
        for (int r = 0; r < 4; r++) {
            float h0, h1;
            upk(acc[r], h0, h1);
            x2[rg + r][2 * jjp]     = fmaxf(h0, 0.f);
            x2[rg + r][2 * jjp + 1] = fmaxf(h1, 0.f);
        }
    }
    __syncthreads();

    if (t < ROWS) {
        const unsigned long long* wp = (const unsigned long long*)fw3;
        const unsigned long long* xp = (const unsigned long long*)&x2[t][0];
        unsigned long long acc = 0ull;
#pragma unroll
        for (int ip = 0; ip < 40; ip++)
            ffma2(acc, xp[ip], __ldg(&wp[ip]));
        float a, b;
        upk(acc, a, b);
        float s = a + b + fb3[0];
        g_logits[row0 + t] = 1.0f / (1.0f + expf(-s));
    }
}

// ---------------- K3: masked softmax ----------------
__global__ void __launch_bounds__(256) softmax_kernel(
    const int* __restrict__ items, float* __restrict__ out)
{
    const int b = blockIdx.x;
    const int t = threadIdx.x;
    const int wid = t >> 5, lane = t & 31;

    __shared__ float red[8];
    __shared__ float s_mx, s_sum;

    float l = g_logits[b * NN + t];
    bool masked = (items[b * NN + t] == 0);
    float val = masked ? -FLT_MAX : l;

    float mx = val;
#pragma unroll
    for (int o = 16; o > 0; o >>= 1)
        mx = fmaxf(mx, __shfl_down_sync(0xffffffffu, mx, o));
    if (lane == 0) red[wid] = mx;
    __syncthreads();
    if (t == 0) {
        float m = red[0];
#pragma unroll
        for (int w = 1; w < 8; w++) m = fmaxf(m, red[w]);
        s_mx = m;
    }
    __syncthreads();
    float m = s_mx;

    float e = masked ? 0.0f : expf(l - m);
    float sum = e;
#pragma unroll
    for (int o = 16; o > 0; o >>= 1)
        sum += __shfl_down_sync(0xffffffffu, sum, o);
    if (lane == 0) red[wid] = sum;
    __syncthreads();
    if (t == 0) {
        float s = 0.0f;
#pragma unroll
        for (int w = 0; w < 8; w++) s += red[w];
        s_sum = s;
    }
    __syncthreads();

    out[b * NN + t] = e / s_sum;
}

// ---------------- launch ----------------
extern "C" void kernel_launch(void* const* d_in, const int* in_sizes, int n_in,
                              void* d_out, int out_size)
{
    const float* emb_user  = (const float*)d_in[0];
    const float* emb_item  = (const float*)d_in[1];
    const float* emb_cate  = (const float*)d_in[2];
    const float* att_w1    = (const float*)d_in[3];
    const float* att_b1    = (const float*)d_in[4];
    const float* att_w2    = (const float*)d_in[5];
    const float* att_b2    = (const float*)d_in[6];
    const float* att_w3    = (const float*)d_in[7];
    const float* att_b3    = (const float*)d_in[8];
    const float* fc_w1     = (const float*)d_in[9];
    const float* fc_b1     = (const float*)d_in[10];
    const float* fc_w2     = (const float*)d_in[11];
    const float* fc_b2     = (const float*)d_in[12];
    const float* fc_w3     = (const float*)d_in[13];
    const float* fc_b3     = (const float*)d_in[14];
    const int*   user      = (const int*)d_in[15];
    const int*   items     = (const int*)d_in[16];
    const int*   items_cate= (const int*)d_in[17];
    const int*   ii        = (const int*)d_in[18];
    const int*   iic       = (const int*)d_in[19];
    float* out = (float*)d_out;

    setup_kernel<<<13, 256>>>(att_w1, att_w2, att_w3, att_b2, att_b3);
    attn_kernel<<<BN, 128>>>(emb_user, emb_item, emb_cate, att_b1,
                             user, items, items_cate, ii, iic);
    fc_kernel<<<BN / ROWS, 256>>>(fc_w1, fc_b1, fc_w2, fc_b2, fc_w3, fc_b3);
    softmax_kernel<<<BB, 256>>>(items, out);
}